// round 11
// baseline (speedup 1.0000x reference)
#include <cuda_runtime.h>
#include <math.h>
#include <stdint.h>

#define T_ENDF   100.0f
#define NTAB     1024
#define NBATCH   16
#define MAXLEN   384
#define NMC      15
#define EPSV     1e-10f
#define U_HALF   46080u

#define BUILD_BLOCKS 128                 /* 8 table intervals per block */
#define PAIR_BLOCKS  768                 /* 16*384 warps / 8 warps per block */
#define MC_BLOCKS    360                 /* 92160 / 256 */
#define PAIR_BASE    BUILD_BLOCKS
#define MC_BASE      (BUILD_BLOCKS + PAIR_BLOCKS)
#define TOTAL_BLOCKS (BUILD_BLOCKS + PAIR_BLOCKS + MC_BLOCKS)

// ---------------- device scratch (no allocations allowed) ----------------
__device__ float4  g_coef[NTAB];
__device__ float   g_part_log[PAIR_BLOCKS];
__device__ float   g_part_int[MC_BLOCKS];
__device__ unsigned g_tab_done;          // static-init 0; finalizer resets to 0
__device__ unsigned g_done;              // static-init 0; finalizer resets to 0

// ---------------- small helpers ----------------
__device__ __forceinline__ float softplusf(float x) {
    return fmaxf(x, 0.f) + log1pf(expf(-fabsf(x)));
}

__device__ __forceinline__ uint32_t rotl32(uint32_t x, int r) {
    return (x << r) | (x >> (32 - r));
}

// packed f32x2 FMA (Blackwell FFMA2): d = a*b + c per 32-bit lane
__device__ __forceinline__ void fma2(unsigned long long& d,
                                     unsigned long long a,
                                     unsigned long long b,
                                     unsigned long long c) {
    asm("fma.rn.f32x2 %0, %1, %2, %3;" : "=l"(d) : "l"(a), "l"(b), "l"(c));
}
__device__ __forceinline__ unsigned long long pack2(float lo, float hi) {
    unsigned long long d;
    asm("mov.b64 %0, {%1, %2};" : "=l"(d) : "r"(__float_as_uint(lo)), "r"(__float_as_uint(hi)));
    return d;
}
__device__ __forceinline__ void unpack2(unsigned long long v, float& lo, float& hi) {
    unsigned a, b;
    asm("mov.b64 {%0, %1}, %2;" : "=r"(a), "=r"(b) : "l"(v));
    lo = __uint_as_float(a); hi = __uint_as_float(b);
}

// Reproduce jax.random.uniform(jax.random.key(42), (15,16,384)) element idx.
__device__ __forceinline__ float jax_uniform(uint32_t idx) {
    const uint32_t k0 = 0u, k1 = 42u;
    const uint32_t k2 = 0x1BD11BDAu ^ k0 ^ k1;
    bool lo = idx < U_HALF;
    uint32_t x0 = lo ? idx : idx - U_HALF;
    uint32_t x1 = lo ? idx + U_HALF : idx;
    x0 += k0; x1 += k1;
#define TF_RND(r) { x0 += x1; x1 = rotl32(x1, r); x1 ^= x0; }
    TF_RND(13) TF_RND(15) TF_RND(26) TF_RND(6);  x0 += k1; x1 += k2 + 1u;
    TF_RND(17) TF_RND(29) TF_RND(16) TF_RND(24); x0 += k2; x1 += k0 + 2u;
    TF_RND(13) TF_RND(15) TF_RND(26) TF_RND(6);  x0 += k0; x1 += k1 + 3u;
    TF_RND(17) TF_RND(29) TF_RND(16) TF_RND(24); x0 += k1; x1 += k2 + 4u;
    TF_RND(13) TF_RND(15) TF_RND(26) TF_RND(6);  x0 += k2; x1 += k0 + 5u;
#undef TF_RND
    uint32_t bits = lo ? x0 : x1;
    return __uint_as_float(0x3f800000u | (bits >> 9)) - 1.0f;
}

// Cubic lookup of f(x), x in [0, 100]: one LDG.128 + 3 FMA.
__device__ __forceinline__ float table_f(float x) {
    const float scale = (float)(NTAB - 1) / T_ENDF;
    float p = x * scale;
    int k = __float2int_rd(p);
    k = max(0, min(k, NTAB - 2));
    float fr = p - (float)k;
    float4 c = g_coef[k];
    return fmaf(fmaf(fmaf(c.w, fr, c.z), fr, c.y), fr, c.x);
}

// ---------------- build helpers ----------------
// Activations stored column-major: act[c*12 + row], row = grid point 0..11.
// Thread (grp, c): grp 0 -> rows 0-5, grp 1 -> rows 6-11.
// Row-pair chunks: grp0 {LDS.128 @f0, LDS.64 @f4}; grp1 {LDS.64 @f6, LDS.128 @f8}.
#define BROWS 12
#define CSTRIDE 12

// One hidden layer on 12 rows x 128 cols via FFMA2.
__device__ __forceinline__ void layer12(const float* __restrict__ As,
                                        float* __restrict__ Cs,
                                        const float* __restrict__ W,
                                        const float* __restrict__ bias,
                                        int tid) {
    const int grp = tid >> 7;            // uniform per warp
    const int c = tid & 127;
    const int f128 = grp * 8;            // float offset of the 4-row chunk
    const int f64  = 4 + grp * 2;        // float offset of the 2-row chunk
    float bv = __ldg(bias + c);
    unsigned long long bp = pack2(bv, bv);
    unsigned long long aL = bp, aH = bp, aS = bp;   // 128.lo-pair, 128.hi-pair, 64-pair
#pragma unroll 4
    for (int k = 0; k < 128; k++) {
        const float* col = As + k * CSTRIDE;
        ulonglong2 v2 = *(const ulonglong2*)(col + f128);   // broadcast LDS.128
        unsigned long long vs = *(const unsigned long long*)(col + f64); // LDS.64
        float w = __ldg(W + k * 128 + c);
        unsigned long long wp = pack2(w, w);
        fma2(aL, v2.x, wp, aL);
        fma2(aH, v2.y, wp, aH);
        fma2(aS, vs,  wp, aS);
    }
    // tanh + store back in the same layout (this thread's c becomes next k)
    float x0, x1;
    float* colo = Cs + c * CSTRIDE;
    unpack2(aL, x0, x1);
    *(unsigned long long*)(colo + f128)     = pack2(tanhf(x0), tanhf(x1));
    unpack2(aH, x0, x1);
    *(unsigned long long*)(colo + f128 + 2) = pack2(tanhf(x0), tanhf(x1));
    unpack2(aS, x0, x1);
    *(unsigned long long*)(colo + f64)      = pack2(tanhf(x0), tanhf(x1));
}

// ---------------- the single kernel ----------------
// bids [0,128): build 8 table intervals each, release g_tab_done.
// bids [128,896): pairs — one warp per (b,i), 8 warps/block.
// bids [896,1256): MC — one thread per (s,b,l).
// Last block to finish reduces partials, writes out, resets counters.
__global__ __launch_bounds__(256) void mega_kernel(
    const float* __restrict__ t, const int* __restrict__ lens,
    const float* __restrict__ bg, float* __restrict__ out,
    const float* __restrict__ W1, const float* __restrict__ b1,
    const float* __restrict__ W2, const float* __restrict__ b2,
    const float* __restrict__ W3, const float* __restrict__ b3,
    const float* __restrict__ W4, const float* __restrict__ b4) {
    __shared__ __align__(16) float A[128 * CSTRIDE];
    __shared__ __align__(16) float C[128 * CSTRIDE];
    __shared__ float val[BROWS];
    __shared__ float wsum[8];
    __shared__ float red[256];
    __shared__ bool  isLast;
    const int tid = threadIdx.x;
    const int bid = blockIdx.x;

    if (bid < BUILD_BLOCKS) {
        // ---------------- builder ----------------
        const float h = T_ENDF / (float)(NTAB - 1);
        const int base = bid * 8 - 1;           // grid-point index of local row 0
        // layer 1: A[c*12 + j] = tanh(x_j * W1[c] + b1[c])
        for (int e = tid; e < BROWS * 128; e += 256) {
            int j = e >> 7, c = e & 127;
            int p = base + j;
            p = max(0, min(p, NTAB - 1));
            float x = (float)p * h;
            A[c * CSTRIDE + j] = tanhf(fmaf(x, __ldg(W1 + c), __ldg(b1 + c)));
        }
        __syncthreads();
        layer12(A, C, W2, b2, tid);   // layer 2
        __syncthreads();
        layer12(C, A, W3, b3, tid);   // layer 3
        __syncthreads();
        if (tid < BROWS * 8) {        // head: 8 threads per row
            int j = tid >> 3, l8 = tid & 7;
            float acc = 0.f;
#pragma unroll
            for (int q = 0; q < 16; q++) {
                int cc = l8 + (q << 3);
                acc = fmaf(A[cc * CSTRIDE + j], __ldg(W4 + cc), acc);
            }
            acc += __shfl_down_sync(0xffffffffu, acc, 4, 8);
            acc += __shfl_down_sync(0xffffffffu, acc, 2, 8);
            acc += __shfl_down_sync(0xffffffffu, acc, 1, 8);
            if (l8 == 0) val[j] = softplusf(acc + __ldg(b4));
        }
        __syncthreads();
        if (tid < 8) {                // Catmull-Rom coefficients
            int k = bid * 8 + tid;
            if (k <= NTAB - 2) {
                float p0 = val[tid], p1 = val[tid + 1], p2 = val[tid + 2], p3 = val[tid + 3];
                float m1 = (k == 0)
                    ? fmaf(-1.5f, p1, fmaf(2.0f, p2, -0.5f * p3))
                    : 0.5f * (p2 - p0);
                float m2 = (k == NTAB - 2)
                    ? fmaf(1.5f, p2, fmaf(-2.0f, p1, 0.5f * p0))
                    : 0.5f * (p3 - p1);
                float d = p2 - p1;
                g_coef[k] = make_float4(p1, m1, 3.f * d - 2.f * m1 - m2, m1 + m2 - 2.f * d);
            }
        }
        __syncthreads();
        if (tid == 0) {               // release table
            __threadfence();
            atomicAdd(&g_tab_done, 1u);
        }
    } else if (bid < MC_BASE) {
        // ---------------- pairs: one warp per (b, i) ----------------
        int wid_in_blk = tid >> 5;
        int lane = tid & 31;
        int wg = (bid - PAIR_BASE) * 8 + wid_in_blk;
        int b = wg / MAXLEN;
        int i = wg % MAXLEN;
        // prologue (independent of table)
        float background = __ldg(bg);
        int len = __ldg(lens + b);
        const float* tb = t + b * MAXLEN;
        float ti = __ldg(tb + i);
        // wait for table
        if (tid == 0) {
            volatile unsigned* p = &g_tab_done;
            while (*p < (unsigned)BUILD_BLOCKS) __nanosleep(256);
        }
        __syncthreads();
        __threadfence();
        float contrib = 0.0f;
        if (i == 0) {
            if (lane == 0) contrib = logf(background);
        } else if (i < len) {
            float s = 0.f;
            for (int j = lane; j < i; j += 32)
                s += table_f(ti - __ldg(tb + j));
#pragma unroll
            for (int o = 16; o; o >>= 1) s += __shfl_down_sync(0xffffffffu, s, o);
            if (lane == 0) contrib = logf(s + background);
        }
        if (lane == 0) wsum[wid_in_blk] = contrib;
        __syncthreads();
        if (tid == 0) {
            float tot = 0.f;
#pragma unroll
            for (int w = 0; w < 8; w++) tot += wsum[w];
            g_part_log[bid - PAIR_BASE] = tot;
        }
    } else {
        // ---------------- MC: one thread per (s, b, l) ----------------
        uint32_t e = (bid - MC_BASE) * 256u + (uint32_t)tid;  // s*6144 + b*384 + l
        uint32_t r = e % (NBATCH * MAXLEN);
        int b = r / MAXLEN;
        int l = r % MAXLEN;
        // prologue: PRNG + loads before the wait
        float u = jax_uniform(e);
        bool valid = (l < __ldg(lens + b));
        float diff = T_ENDF - __ldg(t + r);
        if (tid == 0) {
            volatile unsigned* p = &g_tab_done;
            while (*p < (unsigned)BUILD_BLOCKS) __nanosleep(256);
        }
        __syncthreads();
        __threadfence();
        float contrib = 0.0f;
        if (valid)
            contrib = (table_f(u * diff) + EPSV) * diff * (1.0f / (float)NMC);
#pragma unroll
        for (int o = 16; o; o >>= 1) contrib += __shfl_down_sync(0xffffffffu, contrib, o);
        if ((tid & 31) == 0) wsum[tid >> 5] = contrib;
        __syncthreads();
        if (tid == 0) {
            float tot = 0.f;
#pragma unroll
            for (int w = 0; w < 8; w++) tot += wsum[w];
            g_part_int[bid - MC_BASE] = tot;
        }
    }

    // ---------------- completion + finalize (all blocks converge here) ----
    if (tid == 0) {
        __threadfence();
        unsigned v = atomicAdd(&g_done, 1u);
        isLast = (v == (unsigned)(TOTAL_BLOCKS - 1));
    }
    __syncthreads();
    if (isLast) {
        float sl = 0.f;
        for (int i2 = tid; i2 < PAIR_BLOCKS; i2 += 256) sl += g_part_log[i2];
        float si = 0.f;
        for (int i2 = tid; i2 < MC_BLOCKS; i2 += 256) si += g_part_int[i2];
        red[tid] = sl;
        __syncthreads();
#pragma unroll
        for (int s2 = 128; s2; s2 >>= 1) {
            if (tid < s2) red[tid] += red[tid + s2];
            __syncthreads();
        }
        float sum_log = red[0];
        __syncthreads();
        red[tid] = si;
        __syncthreads();
#pragma unroll
        for (int s2 = 128; s2; s2 >>= 1) {
            if (tid < s2) red[tid] += red[tid + s2];
            __syncthreads();
        }
        if (tid == 0) {
            double ints = (double)red[0] + (double)NBATCH * 100.0 * (double)__ldg(bg);
            out[0] = (float)(-((double)sum_log - ints) / (double)NBATCH);
            g_done = 0u;          // leave-clean for next graph replay
            g_tab_done = 0u;
        }
    }
}

// ---------------- launch ----------------
extern "C" void kernel_launch(void* const* d_in, const int* in_sizes, int n_in,
                              void* d_out, int out_size) {
    const float* seq_pads  = (const float*)d_in[0];   // [16,384,1]
    const int*   seq_lens  = (const int*)  d_in[1];   // [16]
    const float* background= (const float*)d_in[2];   // [1]
    const float* W1 = (const float*)d_in[3];
    const float* b1 = (const float*)d_in[4];
    const float* W2 = (const float*)d_in[5];
    const float* b2 = (const float*)d_in[6];
    const float* W3 = (const float*)d_in[7];
    const float* b3 = (const float*)d_in[8];
    const float* W4 = (const float*)d_in[9];
    const float* b4 = (const float*)d_in[10];
    float* out = (float*)d_out;

    mega_kernel<<<TOTAL_BLOCKS, 256>>>(seq_pads, seq_lens, background, out,
                                       W1, b1, W2, b2, W3, b3, W4, b4);
}

// round 13
// speedup vs baseline: 1.2061x; 1.2061x over previous
#include <cuda_runtime.h>
#include <math.h>
#include <stdint.h>

#define T_ENDF   100.0f
#define NTAB     1024
#define NBATCH   16
#define MAXLEN   384
#define NMC      15
#define EPSV     1e-10f
#define U_HALF   46080u

#define BUILD_BLOCKS 128                 /* 8 table intervals per block */
#define PAIR_BLOCKS  384                 /* 3072 warps x 2 tasks = 6144 (b,i) */
#define MC_BLOCKS    180                 /* 46080 threads x 2 samples = 92160 */
#define PAIR_BASE    BUILD_BLOCKS
#define MC_BASE      (BUILD_BLOCKS + PAIR_BLOCKS)
#define TOTAL_BLOCKS (BUILD_BLOCKS + PAIR_BLOCKS + MC_BLOCKS)
#define PAIR_WARPS   (PAIR_BLOCKS * 8)   /* 3072 */

// ---------------- device scratch (no allocations allowed) ----------------
__device__ float4  g_coef[NTAB];
__device__ float   g_part_log[PAIR_BLOCKS];
__device__ float   g_part_int[MC_BLOCKS];
__device__ unsigned g_tab_done;          // static-init 0; finalizer resets to 0
__device__ unsigned g_done;              // static-init 0; finalizer resets to 0

// ---------------- small helpers ----------------
__device__ __forceinline__ float softplusf(float x) {
    return fmaxf(x, 0.f) + log1pf(expf(-fabsf(x)));
}

__device__ __forceinline__ uint32_t rotl32(uint32_t x, int r) {
    return (x << r) | (x >> (32 - r));
}

// One threefry2x32 call yields BOTH jax uniforms for indices idx and
// idx + 46080 (they are out0/out1 of the same counter pair).
// Valid for idx in [0, 46080).
__device__ __forceinline__ float2 jax_uniform_pair(uint32_t idx) {
    const uint32_t k0 = 0u, k1 = 42u;
    const uint32_t k2 = 0x1BD11BDAu ^ k0 ^ k1;
    uint32_t x0 = idx;
    uint32_t x1 = idx + U_HALF;
    x0 += k0; x1 += k1;
#define TF_RND(r) { x0 += x1; x1 = rotl32(x1, r); x1 ^= x0; }
    TF_RND(13) TF_RND(15) TF_RND(26) TF_RND(6);  x0 += k1; x1 += k2 + 1u;
    TF_RND(17) TF_RND(29) TF_RND(16) TF_RND(24); x0 += k2; x1 += k0 + 2u;
    TF_RND(13) TF_RND(15) TF_RND(26) TF_RND(6);  x0 += k0; x1 += k1 + 3u;
    TF_RND(17) TF_RND(29) TF_RND(16) TF_RND(24); x0 += k1; x1 += k2 + 4u;
    TF_RND(13) TF_RND(15) TF_RND(26) TF_RND(6);  x0 += k2; x1 += k0 + 5u;
#undef TF_RND
    float2 uv;
    uv.x = __uint_as_float(0x3f800000u | (x0 >> 9)) - 1.0f;
    uv.y = __uint_as_float(0x3f800000u | (x1 >> 9)) - 1.0f;
    return uv;
}

// Cubic lookup of f(x), x in [0, 100]: one LDG.128 + 3 FMA.
__device__ __forceinline__ float table_f(float x) {
    const float scale = (float)(NTAB - 1) / T_ENDF;
    float p = x * scale;
    int k = __float2int_rd(p);
    k = max(0, min(k, NTAB - 2));
    float fr = p - (float)k;
    float4 c = g_coef[k];
    return fmaf(fmaf(fmaf(c.w, fr, c.z), fr, c.y), fr, c.x);
}

// ---------------- build helpers (proven round-9 shape, 12 rows) ----------
#define BROWS 12
#define ASTRIDE 132   /* multiple of 4 for LDS.128; broadcast reads: no conflicts */

__device__ __forceinline__ void layer12(const float* __restrict__ Ash,
                                        float* __restrict__ Csh,
                                        const float* __restrict__ W,
                                        const float* __restrict__ bias,
                                        int tid) {
    int grp = tid >> 7;          // 0: rows 0-5, 1: rows 6-11
    int c = tid & 127;
    int r0 = grp * 6;
    float acc[6];
    float bv = __ldg(bias + c);
#pragma unroll
    for (int q = 0; q < 6; q++) acc[q] = bv;
    for (int k4 = 0; k4 < 32; k4++) {
        float w0 = __ldg(W + (k4 * 4 + 0) * 128 + c);
        float w1 = __ldg(W + (k4 * 4 + 1) * 128 + c);
        float w2 = __ldg(W + (k4 * 4 + 2) * 128 + c);
        float w3 = __ldg(W + (k4 * 4 + 3) * 128 + c);
#pragma unroll
        for (int q = 0; q < 6; q++) {
            float4 a = *(const float4*)(Ash + (r0 + q) * ASTRIDE + k4 * 4);
            acc[q] = fmaf(a.x, w0, acc[q]);
            acc[q] = fmaf(a.y, w1, acc[q]);
            acc[q] = fmaf(a.z, w2, acc[q]);
            acc[q] = fmaf(a.w, w3, acc[q]);
        }
    }
#pragma unroll
    for (int q = 0; q < 6; q++)
        Csh[(r0 + q) * ASTRIDE + c] = tanhf(acc[q]);
}

// ---------------- the single kernel ----------------
// bids [0,128): build 8 table intervals each, release g_tab_done.
// bids [128,512): pairs — one warp per TWO (b,i) tasks, 8 warps/block.
// bids [512,692): MC — one thread per TWO samples (e, e+46080).
// Last block to finish reduces partials, writes out, resets counters.
__global__ __launch_bounds__(256) void mega_kernel(
    const float* __restrict__ t, const int* __restrict__ lens,
    const float* __restrict__ bg, float* __restrict__ out,
    const float* __restrict__ W1, const float* __restrict__ b1,
    const float* __restrict__ W2, const float* __restrict__ b2,
    const float* __restrict__ W3, const float* __restrict__ b3,
    const float* __restrict__ W4, const float* __restrict__ b4) {
    __shared__ __align__(16) float A[BROWS * ASTRIDE];
    __shared__ __align__(16) float C[BROWS * ASTRIDE];
    __shared__ float val[BROWS];
    __shared__ float wsum[8];
    __shared__ float red[256];
    __shared__ bool  isLast;
    const int tid = threadIdx.x;
    const int bid = blockIdx.x;

    if (bid < BUILD_BLOCKS) {
        // ---------------- builder ----------------
        const float h = T_ENDF / (float)(NTAB - 1);
        const int base = bid * 8 - 1;           // grid-point index of local row 0
        for (int e = tid; e < BROWS * 128; e += 256) {
            int j = e >> 7, c = e & 127;
            int p = base + j;
            p = max(0, min(p, NTAB - 1));
            float x = (float)p * h;
            A[j * ASTRIDE + c] = tanhf(fmaf(x, __ldg(W1 + c), __ldg(b1 + c)));
        }
        __syncthreads();
        layer12(A, C, W2, b2, tid);   // layer 2
        __syncthreads();
        layer12(C, A, W3, b3, tid);   // layer 3
        __syncthreads();
        if (tid < BROWS * 8) {        // head: 8 threads per row
            int j = tid >> 3, l8 = tid & 7;
            float acc = 0.f;
#pragma unroll
            for (int q = 0; q < 16; q++) {
                int cc = l8 + (q << 3);
                acc = fmaf(A[j * ASTRIDE + cc], __ldg(W4 + cc), acc);
            }
            acc += __shfl_down_sync(0xffffffffu, acc, 4, 8);
            acc += __shfl_down_sync(0xffffffffu, acc, 2, 8);
            acc += __shfl_down_sync(0xffffffffu, acc, 1, 8);
            if (l8 == 0) val[j] = softplusf(acc + __ldg(b4));
        }
        __syncthreads();
        if (tid < 8) {                // Catmull-Rom coefficients
            int k = bid * 8 + tid;
            if (k <= NTAB - 2) {
                float p0 = val[tid], p1 = val[tid + 1], p2 = val[tid + 2], p3 = val[tid + 3];
                float m1 = (k == 0)
                    ? fmaf(-1.5f, p1, fmaf(2.0f, p2, -0.5f * p3))
                    : 0.5f * (p2 - p0);
                float m2 = (k == NTAB - 2)
                    ? fmaf(1.5f, p2, fmaf(-2.0f, p1, 0.5f * p0))
                    : 0.5f * (p3 - p1);
                float d = p2 - p1;
                g_coef[k] = make_float4(p1, m1, 3.f * d - 2.f * m1 - m2, m1 + m2 - 2.f * d);
            }
        }
        __syncthreads();
        if (tid == 0) {               // release table
            __threadfence();
            atomicAdd(&g_tab_done, 1u);
        }
    } else if (bid < MC_BASE) {
        // ---------------- pairs: one warp per TWO (b, i) tasks ------------
        int wid_in_blk = tid >> 5;
        int lane = tid & 31;
        int wg = (bid - PAIR_BASE) * 8 + wid_in_blk;   // [0, 3072)
        // task0: (b0, i), task1: (b0+8, i) since wg+3072 adds 8 batches
        int b0 = wg / MAXLEN;
        int i  = wg % MAXLEN;
        int b1i = b0 + (PAIR_WARPS / MAXLEN);          // +8
        // prologue (independent of table)
        float background = __ldg(bg);
        int len0 = __ldg(lens + b0);
        int len1 = __ldg(lens + b1i);
        const float* tb0 = t + b0 * MAXLEN;
        const float* tb1 = t + b1i * MAXLEN;
        float ti0 = __ldg(tb0 + i);
        float ti1 = __ldg(tb1 + i);
        // wait for table
        if (tid == 0) {
            volatile unsigned* p = &g_tab_done;
            while (*p < (unsigned)BUILD_BLOCKS) __nanosleep(256);
        }
        __syncthreads();
        __threadfence();
        float contrib = 0.0f;
        if (i == 0) {
            if (lane == 0) contrib = 2.0f * logf(background);
        } else {
            float s0 = 0.f, s1 = 0.f;
            for (int j = lane; j < i; j += 32) {
                if (j < len0 || true) {} // (t values past len are 0-padded; mask by i<len below)
                s0 += table_f(ti0 - __ldg(tb0 + j));
                s1 += table_f(ti1 - __ldg(tb1 + j));
            }
#pragma unroll
            for (int o = 16; o; o >>= 1) {
                s0 += __shfl_down_sync(0xffffffffu, s0, o);
                s1 += __shfl_down_sync(0xffffffffu, s1, o);
            }
            if (lane == 0) {
                float c0 = (i < len0) ? logf(s0 + background) : 0.f;
                float c1 = (i < len1) ? logf(s1 + background) : 0.f;
                contrib = c0 + c1;
            }
        }
        if (lane == 0) wsum[wid_in_blk] = contrib;
        __syncthreads();
        if (tid == 0) {
            float tot = 0.f;
#pragma unroll
            for (int w = 0; w < 8; w++) tot += wsum[w];
            g_part_log[bid - PAIR_BASE] = tot;
        }
    } else {
        // ---------------- MC: one thread per TWO samples ------------------
        uint32_t e = (bid - MC_BASE) * 256u + (uint32_t)tid;   // [0, 46080)
        uint32_t r0i = e % (NBATCH * MAXLEN);
        uint32_t r1i = (e + U_HALF) % (NBATCH * MAXLEN);
        int b0 = r0i / MAXLEN, l0 = r0i % MAXLEN;
        int b1i = r1i / MAXLEN, l1 = r1i % MAXLEN;
        // prologue: PRNG + loads before the wait
        float2 u = jax_uniform_pair(e);
        bool v0 = (l0 < __ldg(lens + b0));
        bool v1 = (l1 < __ldg(lens + b1i));
        float d0 = T_ENDF - __ldg(t + r0i);
        float d1 = T_ENDF - __ldg(t + r1i);
        if (tid == 0) {
            volatile unsigned* p = &g_tab_done;
            while (*p < (unsigned)BUILD_BLOCKS) __nanosleep(256);
        }
        __syncthreads();
        __threadfence();
        float contrib = 0.0f;
        if (v0) contrib += (table_f(u.x * d0) + EPSV) * d0 * (1.0f / (float)NMC);
        if (v1) contrib += (table_f(u.y * d1) + EPSV) * d1 * (1.0f / (float)NMC);
#pragma unroll
        for (int o = 16; o; o >>= 1) contrib += __shfl_down_sync(0xffffffffu, contrib, o);
        if ((tid & 31) == 0) wsum[tid >> 5] = contrib;
        __syncthreads();
        if (tid == 0) {
            float tot = 0.f;
#pragma unroll
            for (int w = 0; w < 8; w++) tot += wsum[w];
            g_part_int[bid - MC_BASE] = tot;
        }
    }

    // ---------------- completion + finalize (all blocks converge here) ----
    if (tid == 0) {
        __threadfence();
        unsigned v = atomicAdd(&g_done, 1u);
        isLast = (v == (unsigned)(TOTAL_BLOCKS - 1));
    }
    __syncthreads();
    if (isLast) {
        float sl = 0.f;
        for (int i2 = tid; i2 < PAIR_BLOCKS; i2 += 256) sl += g_part_log[i2];
        float si = 0.f;
        for (int i2 = tid; i2 < MC_BLOCKS; i2 += 256) si += g_part_int[i2];
        red[tid] = sl;
        __syncthreads();
#pragma unroll
        for (int s2 = 128; s2; s2 >>= 1) {
            if (tid < s2) red[tid] += red[tid + s2];
            __syncthreads();
        }
        float sum_log = red[0];
        __syncthreads();
        red[tid] = si;
        __syncthreads();
#pragma unroll
        for (int s2 = 128; s2; s2 >>= 1) {
            if (tid < s2) red[tid] += red[tid + s2];
            __syncthreads();
        }
        if (tid == 0) {
            double ints = (double)red[0] + (double)NBATCH * 100.0 * (double)__ldg(bg);
            out[0] = (float)(-((double)sum_log - ints) / (double)NBATCH);
            g_done = 0u;          // leave-clean for next graph replay
            g_tab_done = 0u;
        }
    }
}

// ---------------- launch ----------------
extern "C" void kernel_launch(void* const* d_in, const int* in_sizes, int n_in,
                              void* d_out, int out_size) {
    const float* seq_pads  = (const float*)d_in[0];   // [16,384,1]
    const int*   seq_lens  = (const int*)  d_in[1];   // [16]
    const float* background= (const float*)d_in[2];   // [1]
    const float* W1 = (const float*)d_in[3];
    const float* b1 = (const float*)d_in[4];
    const float* W2 = (const float*)d_in[5];
    const float* b2 = (const float*)d_in[6];
    const float* W3 = (const float*)d_in[7];
    const float* b3 = (const float*)d_in[8];
    const float* W4 = (const float*)d_in[9];
    const float* b4 = (const float*)d_in[10];
    float* out = (float*)d_out;

    mega_kernel<<<TOTAL_BLOCKS, 256>>>(seq_pads, seq_lens, background, out,
                                       W1, b1, W2, b2, W3, b3, W4, b4);
}

// round 14
// speedup vs baseline: 1.3889x; 1.1515x over previous
#include <cuda_runtime.h>
#include <math.h>
#include <stdint.h>

#define T_ENDF   100.0f
#define NTAB     512
#define NBATCH   16
#define MAXLEN   384
#define NMC      15
#define EPSV     1e-10f
#define U_HALF   46080u

#define BUILD_BLOCKS 128                 /* 4 table intervals per block */
#define CONS_BLOCKS  384                 /* pairs (2 tasks/warp) + MC (120 thr/block) */
#define CONS_BASE    BUILD_BLOCKS
#define TOTAL_BLOCKS (BUILD_BLOCKS + CONS_BLOCKS)
#define PAIR_WARPS   (CONS_BLOCKS * 8)   /* 3072 */
#define MC_PER_BLOCK 120                 /* 384*120 = 46080 sample-pairs */

// ---------------- device scratch (no allocations allowed) ----------------
__device__ float4  g_coef[NTAB];
__device__ float   g_part_log[CONS_BLOCKS];
__device__ float   g_part_int[CONS_BLOCKS];
__device__ unsigned g_tab_done;          // static-init 0; finalizer resets to 0
__device__ unsigned g_done;              // static-init 0; finalizer resets to 0

// ---------------- small helpers ----------------
__device__ __forceinline__ float softplusf(float x) {
    return fmaxf(x, 0.f) + log1pf(expf(-fabsf(x)));
}

__device__ __forceinline__ uint32_t rotl32(uint32_t x, int r) {
    return (x << r) | (x >> (32 - r));
}

// One threefry2x32 call yields BOTH jax uniforms for indices idx and
// idx + 46080 (out0/out1 of the same counter pair). idx in [0, 46080).
__device__ __forceinline__ float2 jax_uniform_pair(uint32_t idx) {
    const uint32_t k0 = 0u, k1 = 42u;
    const uint32_t k2 = 0x1BD11BDAu ^ k0 ^ k1;
    uint32_t x0 = idx;
    uint32_t x1 = idx + U_HALF;
    x0 += k0; x1 += k1;
#define TF_RND(r) { x0 += x1; x1 = rotl32(x1, r); x1 ^= x0; }
    TF_RND(13) TF_RND(15) TF_RND(26) TF_RND(6);  x0 += k1; x1 += k2 + 1u;
    TF_RND(17) TF_RND(29) TF_RND(16) TF_RND(24); x0 += k2; x1 += k0 + 2u;
    TF_RND(13) TF_RND(15) TF_RND(26) TF_RND(6);  x0 += k0; x1 += k1 + 3u;
    TF_RND(17) TF_RND(29) TF_RND(16) TF_RND(24); x0 += k1; x1 += k2 + 4u;
    TF_RND(13) TF_RND(15) TF_RND(26) TF_RND(6);  x0 += k2; x1 += k0 + 5u;
#undef TF_RND
    float2 uv;
    uv.x = __uint_as_float(0x3f800000u | (x0 >> 9)) - 1.0f;
    uv.y = __uint_as_float(0x3f800000u | (x1 >> 9)) - 1.0f;
    return uv;
}

// Cubic lookup of f(x), x in [0, 100]: one LDG.128 + 3 FMA.
__device__ __forceinline__ float table_f(float x) {
    const float scale = (float)(NTAB - 1) / T_ENDF;
    float p = x * scale;
    int k = __float2int_rd(p);
    k = max(0, min(k, NTAB - 2));
    float fr = p - (float)k;
    float4 c = g_coef[k];
    return fmaf(fmaf(fmaf(c.w, fr, c.z), fr, c.y), fr, c.x);
}

// ---------------- build helpers (8 rows: 4 intervals + halo) ----------
#define BROWS 8
#define ASTRIDE 132   /* multiple of 4 for LDS.128; broadcast reads: no conflicts */

__device__ __forceinline__ void layer8(const float* __restrict__ Ash,
                                       float* __restrict__ Csh,
                                       const float* __restrict__ W,
                                       const float* __restrict__ bias,
                                       int tid) {
    int grp = tid >> 7;          // 0: rows 0-3, 1: rows 4-7
    int c = tid & 127;
    int r0 = grp * 4;
    float acc[4];
    float bv = __ldg(bias + c);
#pragma unroll
    for (int q = 0; q < 4; q++) acc[q] = bv;
    for (int k4 = 0; k4 < 32; k4++) {
        float w0 = __ldg(W + (k4 * 4 + 0) * 128 + c);
        float w1 = __ldg(W + (k4 * 4 + 1) * 128 + c);
        float w2 = __ldg(W + (k4 * 4 + 2) * 128 + c);
        float w3 = __ldg(W + (k4 * 4 + 3) * 128 + c);
#pragma unroll
        for (int q = 0; q < 4; q++) {
            float4 a = *(const float4*)(Ash + (r0 + q) * ASTRIDE + k4 * 4);
            acc[q] = fmaf(a.x, w0, acc[q]);
            acc[q] = fmaf(a.y, w1, acc[q]);
            acc[q] = fmaf(a.z, w2, acc[q]);
            acc[q] = fmaf(a.w, w3, acc[q]);
        }
    }
#pragma unroll
    for (int q = 0; q < 4; q++)
        Csh[(r0 + q) * ASTRIDE + c] = tanhf(acc[q]);
}

// ---------------- the single kernel ----------------
// bids [0,128): build 4 table intervals each, release g_tab_done.
// bids [128,512): consumers — pairs: one warp per TWO (b,i) tasks (8 warps),
//                 MC: threads tid<120 each handle sample-pair (e, e+46080).
// Last block to finish reduces partials, writes out, resets counters.
__global__ __launch_bounds__(256) void mega_kernel(
    const float* __restrict__ t, const int* __restrict__ lens,
    const float* __restrict__ bg, float* __restrict__ out,
    const float* __restrict__ W1, const float* __restrict__ b1,
    const float* __restrict__ W2, const float* __restrict__ b2,
    const float* __restrict__ W3, const float* __restrict__ b3,
    const float* __restrict__ W4, const float* __restrict__ b4) {
    __shared__ __align__(16) float A[BROWS * ASTRIDE];
    __shared__ __align__(16) float C[BROWS * ASTRIDE];
    __shared__ float val[BROWS];
    __shared__ float wlog[8];
    __shared__ float wint[4];
    __shared__ bool  isLast;
    const int tid = threadIdx.x;
    const int bid = blockIdx.x;

    if (bid < BUILD_BLOCKS) {
        // ---------------- builder ----------------
        const float h = T_ENDF / (float)(NTAB - 1);
        const int base = bid * 4 - 1;           // grid-point index of local row 0
        for (int e = tid; e < BROWS * 128; e += 256) {
            int j = e >> 7, c = e & 127;
            int p = base + j;
            p = max(0, min(p, NTAB - 1));
            float x = (float)p * h;
            A[j * ASTRIDE + c] = tanhf(fmaf(x, __ldg(W1 + c), __ldg(b1 + c)));
        }
        __syncthreads();
        layer8(A, C, W2, b2, tid);    // layer 2
        __syncthreads();
        layer8(C, A, W3, b3, tid);    // layer 3
        __syncthreads();
        if (tid < BROWS * 8) {        // head: 8 threads per row
            int j = tid >> 3, l8 = tid & 7;
            float acc = 0.f;
#pragma unroll
            for (int q = 0; q < 16; q++) {
                int cc = l8 + (q << 3);
                acc = fmaf(A[j * ASTRIDE + cc], __ldg(W4 + cc), acc);
            }
            acc += __shfl_down_sync(0xffffffffu, acc, 4, 8);
            acc += __shfl_down_sync(0xffffffffu, acc, 2, 8);
            acc += __shfl_down_sync(0xffffffffu, acc, 1, 8);
            if (l8 == 0) val[j] = softplusf(acc + __ldg(b4));
        }
        __syncthreads();
        if (tid < 4) {                // Catmull-Rom coefficients
            int k = bid * 4 + tid;
            if (k <= NTAB - 2) {
                float p0 = val[tid], p1 = val[tid + 1], p2 = val[tid + 2], p3 = val[tid + 3];
                float m1 = (k == 0)
                    ? fmaf(-1.5f, p1, fmaf(2.0f, p2, -0.5f * p3))
                    : 0.5f * (p2 - p0);
                float m2 = (k == NTAB - 2)
                    ? fmaf(1.5f, p2, fmaf(-2.0f, p1, 0.5f * p0))
                    : 0.5f * (p3 - p1);
                float d = p2 - p1;
                g_coef[k] = make_float4(p1, m1, 3.f * d - 2.f * m1 - m2, m1 + m2 - 2.f * d);
            }
        }
        __syncthreads();
        if (tid == 0) {               // release table
            __threadfence();
            atomicAdd(&g_tab_done, 1u);
        }
    } else {
        // ---------------- consumer: pairs + MC in one block ---------------
        const int p = bid - CONS_BASE;          // [0, 384)
        const int wid_in_blk = tid >> 5;
        const int lane = tid & 31;
        // pairs task ids
        int wg = p * 8 + wid_in_blk;            // [0, 3072)
        int b0 = wg / MAXLEN;
        int i  = wg % MAXLEN;
        int b1i = b0 + (PAIR_WARPS / MAXLEN);   // +8
        // ---- prologue (independent of table) ----
        float background = __ldg(bg);
        int len0 = __ldg(lens + b0);
        int len1 = __ldg(lens + b1i);
        const float* tb0 = t + b0 * MAXLEN;
        const float* tb1 = t + b1i * MAXLEN;
        float ti0 = __ldg(tb0 + i);
        float ti1 = __ldg(tb1 + i);
        // MC prologue: PRNG + loads for threads tid < 120
        float2 u = make_float2(0.f, 0.f);
        float d0 = 0.f, d1 = 0.f;
        bool v0 = false, v1 = false;
        if (tid < MC_PER_BLOCK) {
            uint32_t e = (uint32_t)(p * MC_PER_BLOCK + tid);     // [0, 46080)
            uint32_t r0i = e % (NBATCH * MAXLEN);
            uint32_t r1i = (e + U_HALF) % (NBATCH * MAXLEN);
            int mb0 = r0i / MAXLEN, ml0 = r0i % MAXLEN;
            int mb1 = r1i / MAXLEN, ml1 = r1i % MAXLEN;
            u = jax_uniform_pair(e);
            v0 = (ml0 < __ldg(lens + mb0));
            v1 = (ml1 < __ldg(lens + mb1));
            d0 = T_ENDF - __ldg(t + r0i);
            d1 = T_ENDF - __ldg(t + r1i);
        }
        // ---- wait for table ----
        if (tid == 0) {
            volatile unsigned* pd = &g_tab_done;
            while (*pd < (unsigned)BUILD_BLOCKS) __nanosleep(128);
        }
        __syncthreads();
        __threadfence();
        // ---- MC compute (warps 0-3 carry contributions) ----
        float ci = 0.f;
        if (tid < MC_PER_BLOCK) {
            if (v0) ci += (table_f(u.x * d0) + EPSV) * d0 * (1.0f / (float)NMC);
            if (v1) ci += (table_f(u.y * d1) + EPSV) * d1 * (1.0f / (float)NMC);
        }
        if (tid < 128) {
#pragma unroll
            for (int o = 16; o; o >>= 1) ci += __shfl_down_sync(0xffffffffu, ci, o);
            if (lane == 0) wint[wid_in_blk] = ci;
        }
        // ---- pairs compute ----
        float cl = 0.0f;
        bool need0 = (i < len0), need1 = (i < len1);
        if (i == 0) {
            if (lane == 0) cl = 2.0f * logf(background);
        } else if (need0 || need1) {
            float s0 = 0.f, s1 = 0.f;
            for (int j = lane; j < i; j += 32) {
                s0 += table_f(ti0 - __ldg(tb0 + j));
                s1 += table_f(ti1 - __ldg(tb1 + j));
            }
#pragma unroll
            for (int o = 16; o; o >>= 1) {
                s0 += __shfl_down_sync(0xffffffffu, s0, o);
                s1 += __shfl_down_sync(0xffffffffu, s1, o);
            }
            if (lane == 0) {
                float c0 = need0 ? logf(s0 + background) : 0.f;
                float c1 = need1 ? logf(s1 + background) : 0.f;
                cl = c0 + c1;
            }
        }
        if (lane == 0) wlog[wid_in_blk] = cl;
        __syncthreads();
        if (tid == 0) {
            float tl = 0.f;
#pragma unroll
            for (int w = 0; w < 8; w++) tl += wlog[w];
            g_part_log[p] = tl;
            float tiv = 0.f;
#pragma unroll
            for (int w = 0; w < 4; w++) tiv += wint[w];
            g_part_int[p] = tiv;
        }
    }

    // ---------------- completion + finalize (all blocks converge here) ----
    if (tid == 0) {
        __threadfence();
        unsigned v = atomicAdd(&g_done, 1u);
        isLast = (v == (unsigned)(TOTAL_BLOCKS - 1));
    }
    __syncthreads();
    if (isLast && tid < 32) {
        float sl = 0.f, si = 0.f;
        for (int j = tid; j < CONS_BLOCKS; j += 32) {
            sl += g_part_log[j];
            si += g_part_int[j];
        }
#pragma unroll
        for (int o = 16; o; o >>= 1) {
            sl += __shfl_down_sync(0xffffffffu, sl, o);
            si += __shfl_down_sync(0xffffffffu, si, o);
        }
        if (tid == 0) {
            double ints = (double)si + (double)NBATCH * 100.0 * (double)__ldg(bg);
            out[0] = (float)(-((double)sl - ints) / (double)NBATCH);
            g_done = 0u;          // leave-clean for next graph replay
            g_tab_done = 0u;
        }
    }
}

// ---------------- launch ----------------
extern "C" void kernel_launch(void* const* d_in, const int* in_sizes, int n_in,
                              void* d_out, int out_size) {
    const float* seq_pads  = (const float*)d_in[0];   // [16,384,1]
    const int*   seq_lens  = (const int*)  d_in[1];   // [16]
    const float* background= (const float*)d_in[2];   // [1]
    const float* W1 = (const float*)d_in[3];
    const float* b1 = (const float*)d_in[4];
    const float* W2 = (const float*)d_in[5];
    const float* b2 = (const float*)d_in[6];
    const float* W3 = (const float*)d_in[7];
    const float* b3 = (const float*)d_in[8];
    const float* W4 = (const float*)d_in[9];
    const float* b4 = (const float*)d_in[10];
    float* out = (float*)d_out;

    mega_kernel<<<TOTAL_BLOCKS, 256>>>(seq_pads, seq_lens, background, out,
                                       W1, b1, W2, b2, W3, b3, W4, b4);
}